// round 4
// baseline (speedup 1.0000x reference)
#include <cuda_runtime.h>
#include <mma.h>
#include <math.h>
#include <stdint.h>

using namespace nvcuda;

#define BB 64
#define TT 128
#define MMM 4
#define DDIM 512
#define HH 512
#define LLAY 2
#define KKC 6
#define FF 2560
#define ROWS 8192

// ===== scratch =====
__device__ float g_hid[3][BB * TT * 2 * HH];
__device__ float g_share[3][BB * TT * HH];
__device__ float g_part[3][BB * 2 * FF];
__device__ float g_w[BB * 2 * KKC];
__device__ float g_cell[BB * 2 * HH];
__device__ float g_sstate[BB * HH];
__device__ float g_cum[BB * HH];
// precomputed input projections, [m]: [j][8192 rows][2560]
__device__ float g_pre0[(size_t)2 * ROWS * FF];   // x_t @ Wx_j
__device__ float g_pre1[(size_t)2 * ROWS * FF];   // X_j @ Wc1_j   (read at row+1)
__device__ float g_pre2[(size_t)2 * ROWS * FF];   // X_{1-j} @ Wc3_j
__device__ float g_pre3[(size_t)2 * ROWS * FF];   // X_{1-j} @ Wc4_j (read at row+1)
__device__ float g_pre4[(size_t)2 * ROWS * FF];   // CTX @ Wc5_j
// tf32 splits
__device__ float g_xh[2][ROWS * DDIM];   // activations hi (current layer)
__device__ float g_xl[2][ROWS * DDIM];
__device__ float g_ch[ROWS * HH];        // context hi
__device__ float g_cl[ROWS * HH];
__device__ float g_wh[(size_t)20 * DDIM * FF];   // weights hi: [(l*2+j)*5+m][512][2560]
__device__ float g_wl[(size_t)20 * DDIM * FF];

__device__ __forceinline__ void split_tf32(float v, float& hi, float& lo) {
    hi = wmma::__float_to_tf32(v);
    lo = wmma::__float_to_tf32(v - hi);
}

// ===== splits =====
__global__ void k_actsplit(int l) {
    size_t i = (size_t)blockIdx.x * blockDim.x + threadIdx.x;
    if (i >= (size_t)2 * ROWS * DDIM) return;
    int j = (int)(i / ((size_t)ROWS * DDIM));
    size_t r = i % ((size_t)ROWS * DDIM);
    size_t row = r >> 9; int d = (int)(r & 511);
    float hi, lo;
    split_tf32(g_hid[l][(row * 2 + j) * DDIM + d], hi, lo);
    g_xh[j][r] = hi; g_xl[j][r] = lo;
}

__global__ void k_ctxsplit(const float* __restrict__ ctx) {
    size_t i = (size_t)blockIdx.x * blockDim.x + threadIdx.x;
    if (i >= (size_t)ROWS * HH) return;
    float hi, lo; split_tf32(ctx[i], hi, lo);
    g_ch[i] = hi; g_cl[i] = lo;
}

__global__ void k_wsplit(const float* __restrict__ Wx, const float* __restrict__ Wc) {
    size_t i = (size_t)blockIdx.x * blockDim.x + threadIdx.x;
    const size_t per = (size_t)DDIM * FF;
    if (i >= 20 * per) return;
    int z = (int)(i / per);
    size_t r = i % per;
    int l = z / 10, j = (z / 5) % 2, m = z % 5;
    float v;
    if (m == 0) v = Wx[(size_t)(l * 2 + j) * per + r];
    else {
        const int kid[5] = {0, 1, 3, 4, 5};
        v = Wc[((size_t)(l * 2 + j) * KKC + kid[m]) * per + r];
    }
    float hi, lo; split_tf32(v, hi, lo);
    g_wh[i] = hi; g_wl[i] = lo;
}

// ===== WMMA 3xTF32 precompute: C[8192,2560] = A[8192,512] @ W[512,2560] =====
// grid (20 ntiles, 64 mtiles, 10 z=(j,m)); 256 thr, 8 warps (4x2), warp tile 32x64
__global__ void __launch_bounds__(256) k_pre(int l) {
    __shared__ float As_h[128][20];
    __shared__ float As_l[128][20];
    __shared__ float Bs_h[16][132];
    __shared__ float Bs_l[16][132];

    const int tid = threadIdx.x;
    const int nt = blockIdx.x, mt = blockIdx.y, z = blockIdx.z;
    const int j = z / 5, m = z % 5;
    const int n0 = nt * 128, row0 = mt * 128;

    const float *Ah, *Al;
    if (m == 4) { Ah = g_ch; Al = g_cl; }
    else { int g = (m < 2) ? j : 1 - j; Ah = g_xh[g]; Al = g_xl[g]; }
    const size_t wz = (size_t)((l * 2 + j) * 5 + m) * DDIM * FF;
    const float* Wh_ = g_wh + wz;
    const float* Wl_ = g_wl + wz;

    const int wid = tid >> 5;
    const int wm = wid >> 1, wn = wid & 1;       // 4 x 2
    const int wrow = wm * 32, wcol = wn * 64;

    wmma::fragment<wmma::accumulator, 16, 16, 8, float> acc[2][4];
#pragma unroll
    for (int i = 0; i < 2; i++)
#pragma unroll
        for (int n = 0; n < 4; n++) wmma::fill_fragment(acc[i][n], 0.f);

    for (int k0 = 0; k0 < 512; k0 += 16) {
        // load A tile 128x16 (hi+lo)
#pragma unroll
        for (int i = 0; i < 2; i++) {
            int fidx = tid + i * 256;        // 0..511 float4 units
            int r = fidx >> 2, c = (fidx & 3) * 4;
            const float4 vh = *(const float4*)(Ah + (size_t)(row0 + r) * 512 + k0 + c);
            const float4 vl = *(const float4*)(Al + (size_t)(row0 + r) * 512 + k0 + c);
            *(float4*)&As_h[r][c] = vh;
            *(float4*)&As_l[r][c] = vl;
        }
        // load B tile 16x128 (hi+lo)
#pragma unroll
        for (int i = 0; i < 2; i++) {
            int fidx = tid + i * 256;
            int r = fidx >> 5, c = (fidx & 31) * 4;
            const float4 vh = *(const float4*)(Wh_ + (size_t)(k0 + r) * FF + n0 + c);
            const float4 vl = *(const float4*)(Wl_ + (size_t)(k0 + r) * FF + n0 + c);
            *(float4*)&Bs_h[r][c] = vh;
            *(float4*)&Bs_l[r][c] = vl;
        }
        __syncthreads();
#pragma unroll
        for (int k8 = 0; k8 < 16; k8 += 8) {
            wmma::fragment<wmma::matrix_a, 16, 16, 8, wmma::precision::tf32, wmma::row_major> ah[2], al[2];
            wmma::fragment<wmma::matrix_b, 16, 16, 8, wmma::precision::tf32, wmma::row_major> bh[4], bl[4];
#pragma unroll
            for (int i = 0; i < 2; i++) {
                wmma::load_matrix_sync(ah[i], &As_h[wrow + i * 16][k8], 20);
                wmma::load_matrix_sync(al[i], &As_l[wrow + i * 16][k8], 20);
            }
#pragma unroll
            for (int n = 0; n < 4; n++) {
                wmma::load_matrix_sync(bh[n], &Bs_h[k8][wcol + n * 16], 132);
                wmma::load_matrix_sync(bl[n], &Bs_l[k8][wcol + n * 16], 132);
            }
#pragma unroll
            for (int i = 0; i < 2; i++)
#pragma unroll
                for (int n = 0; n < 4; n++) {
                    wmma::mma_sync(acc[i][n], ah[i], bh[n], acc[i][n]);
                    wmma::mma_sync(acc[i][n], ah[i], bl[n], acc[i][n]);
                    wmma::mma_sync(acc[i][n], al[i], bh[n], acc[i][n]);
                }
        }
        __syncthreads();
    }
    float* dst;
    switch (m) { case 0: dst = g_pre0; break; case 1: dst = g_pre1; break;
                 case 2: dst = g_pre2; break; case 3: dst = g_pre3; break;
                 default: dst = g_pre4; }
    dst += ((size_t)j * ROWS) * FF;
#pragma unroll
    for (int i = 0; i < 2; i++)
#pragma unroll
        for (int n = 0; n < 4; n++)
            wmma::store_matrix_sync(dst + (size_t)(row0 + wrow + i * 16) * FF + n0 + wcol + n * 16,
                                    acc[i][n], FF, wmma::mem_row_major);
}

// ===== share_feat GEMM (fp32) =====
__global__ void k_share(const float* __restrict__ A, const float* __restrict__ W,
                        const float* __restrict__ bias) {
    __shared__ float As[16][64];
    __shared__ float Ws[16][128];
    const int n0 = blockIdx.x * 128, m0 = blockIdx.y * 64;
    const int tid = threadIdx.x;
    const int ty = tid >> 4, tx = tid & 15;
    const int lm = tid & 63, lk = (tid >> 6) * 8;
    float acc[8][8];
#pragma unroll
    for (int i = 0; i < 8; i++)
#pragma unroll
        for (int jj = 0; jj < 8; jj++) acc[i][jj] = 0.f;
    for (int k0 = 0; k0 < 2048; k0 += 16) {
        const float* ap = A + (size_t)(m0 + lm) * 2048 + k0 + lk;
        float4 a0 = *(const float4*)ap;
        float4 a1 = *(const float4*)(ap + 4);
        As[lk + 0][lm] = a0.x; As[lk + 1][lm] = a0.y; As[lk + 2][lm] = a0.z; As[lk + 3][lm] = a0.w;
        As[lk + 4][lm] = a1.x; As[lk + 5][lm] = a1.y; As[lk + 6][lm] = a1.z; As[lk + 7][lm] = a1.w;
#pragma unroll
        for (int q = 0; q < 4; q++) {
            int fi = tid + q * 128;
            int wk = fi >> 5, wn = (fi & 31) * 4;
            *(float4*)&Ws[wk][wn] = *(const float4*)(W + (size_t)(k0 + wk) * 512 + n0 + wn);
        }
        __syncthreads();
#pragma unroll
        for (int k = 0; k < 16; k++) {
            float a[8], w[8];
#pragma unroll
            for (int i = 0; i < 8; i++) a[i] = As[k][ty + i * 8];
#pragma unroll
            for (int jj = 0; jj < 8; jj++) w[jj] = Ws[k][tx + jj * 16];
#pragma unroll
            for (int i = 0; i < 8; i++)
#pragma unroll
                for (int jj = 0; jj < 8; jj++) acc[i][jj] = fmaf(a[i], w[jj], acc[i][jj]);
        }
        __syncthreads();
    }
#pragma unroll
    for (int i = 0; i < 8; i++) {
        int r = m0 + ty + i * 8;
#pragma unroll
        for (int jj = 0; jj < 8; jj++) {
            int cn = n0 + tx + jj * 16;
            g_share[0][(size_t)r * 512 + cn] = fmaxf(acc[i][jj] + bias[cn], 0.f);
        }
    }
}

// ===== group separation =====
__global__ void k_groupsep(const float* __restrict__ feat, const float* __restrict__ sepW,
                           const float* __restrict__ sepb) {
    const int bt = blockIdx.x;
    const int tid = threadIdx.x;
    const int warp = tid >> 5, lane = tid & 31;
    __shared__ float sm[4];
    const float* fr = feat + (size_t)bt * MMM * DDIM;
    if (warp < 4) {
        float s = 0.f;
        const float* f = fr + warp * DDIM;
        for (int d = lane; d < DDIM; d += 32) s += f[d] * sepW[d];
        for (int o = 16; o; o >>= 1) s += __shfl_down_sync(0xffffffffu, s, o);
        if (lane == 0) sm[warp] = s + sepb[0];
    }
    __syncthreads();
    float sc0 = sm[0], sc1 = sm[1], sc2 = sm[2], sc3 = sm[3];
    float mx = fmaxf(fmaxf(sc0, sc1), fmaxf(sc2, sc3));
    float e0 = expf(sc0 - mx), e1 = expf(sc1 - mx), e2 = expf(sc2 - mx), e3 = expf(sc3 - mx);
    float inv = 1.f / (e0 + e1 + e2 + e3);
    float w0 = (e0 * inv - 0.25f) > 0.f ? 1.f : 0.f;
    float w1 = (e1 * inv - 0.25f) > 0.f ? 1.f : 0.f;
    float w2 = (e2 * inv - 0.25f) > 0.f ? 1.f : 0.f;
    float w3 = (e3 * inv - 0.25f) > 0.f ? 1.f : 0.f;
    float n0 = w0 + w1 + w2 + w3;
    float d0 = n0 + 1e-8f, d1 = (4.f - n0) + 1e-8f;
    for (int d = tid; d < DDIM; d += 128) {
        float f0 = fr[d], f1 = fr[DDIM + d], f2 = fr[2 * DDIM + d], f3 = fr[3 * DDIM + d];
        g_hid[0][((size_t)bt * 2 + 0) * DDIM + d] = (w0 * f0 + w1 * f1 + w2 * f2 + w3 * f3) / d0;
        g_hid[0][((size_t)bt * 2 + 1) * DDIM + d] =
            ((1.f - w0) * f0 + (1.f - w1) * f1 + (1.f - w2) * f2 + (1.f - w3) * f3) / d1;
    }
}

// ===== per-layer init: states + t=0 gating (logits = ab) =====
__global__ void k_layerinit(int l, const float* __restrict__ ab) {
    int i = blockIdx.x * blockDim.x + threadIdx.x;
    if (i < BB * 2 * HH) g_cell[i] = 0.f;
    if (i < BB * HH) { g_sstate[i] = 0.f; g_cum[i] = 0.f; }
    if (blockIdx.x == 0) {
        __shared__ int si1, si2;
        if (threadIdx.x == 0) {
            const float* a = ab + l * KKC;
            int i1 = 0;
            for (int k = 1; k < KKC; k++) if (a[k] > a[i1]) i1 = k;
            int i2 = (i1 == 0) ? 1 : 0;
            for (int k = 0; k < KKC; k++) if (k != i1 && a[k] > a[i2]) i2 = k;
            si1 = i1; si2 = i2;
        }
        __syncthreads();
        for (int idx = threadIdx.x; idx < BB * 2 * KKC; idx += blockDim.x) {
            int k = idx % KKC;
            g_w[idx] = (k == si1 || k == si2) ? 0.5f : 0.f;
        }
    }
}

// ===== scan: recurrent GEMM (3 chunks, fp32 exact) =====
__global__ void k_stepgemm(int l, int t, const float* __restrict__ Wh, const float* __restrict__ Wc) {
    const int n0 = blockIdx.x * 128;
    const int j = blockIdx.y;
    const int c = blockIdx.z;
    const float* hout = g_hid[l + 1];
    const float* Wmat = (c == 0) ? Wh + (size_t)(l * 2 + j) * DDIM * FF
                                 : Wc + ((size_t)(l * 2 + j) * KKC + (c == 1 ? 0 : 2)) * DDIM * FF;

    __shared__ const float* sp[64];
    __shared__ float scs[64];
    __shared__ float As[16][64];
    __shared__ float Ws[16][128];

    const int tid = threadIdx.x;
    if (tid < 64) {
        const int b = tid;
        const float* p = 0; float s = 1.f;
        if (c == 0) {
            p = (t > 0) ? hout + ((size_t)(b * TT + t - 1) * 2 + j) * DDIM : 0;
        } else if (c == 1) {
            p = (t > 1) ? hout + ((size_t)(b * TT + t - 2) * 2 + j) * DDIM : 0;
            s = g_w[(b * 2 + j) * KKC + 0];
        } else {
            p = (t > 0) ? hout + ((size_t)(b * TT + t - 1) * 2 + (1 - j)) * DDIM : 0;
            s = g_w[(b * 2 + j) * KKC + 2];
        }
        if (s == 0.f) p = 0;
        sp[b] = p; scs[b] = s;
    }
    __syncthreads();

    const int ty = tid >> 4, tx = tid & 15;
    const int lm = tid & 63, lk = (tid >> 6) * 8;
    float acc[8][8];
#pragma unroll
    for (int i = 0; i < 8; i++)
#pragma unroll
        for (int jj = 0; jj < 8; jj++) acc[i][jj] = 0.f;
    const float* myp = sp[lm];
    const float mys = scs[lm];

    for (int k0 = 0; k0 < 512; k0 += 16) {
        float4 a0 = make_float4(0.f, 0.f, 0.f, 0.f), a1 = a0;
        if (myp) { a0 = *(const float4*)(myp + k0 + lk); a1 = *(const float4*)(myp + k0 + lk + 4); }
        As[lk + 0][lm] = a0.x * mys; As[lk + 1][lm] = a0.y * mys;
        As[lk + 2][lm] = a0.z * mys; As[lk + 3][lm] = a0.w * mys;
        As[lk + 4][lm] = a1.x * mys; As[lk + 5][lm] = a1.y * mys;
        As[lk + 6][lm] = a1.z * mys; As[lk + 7][lm] = a1.w * mys;
#pragma unroll
        for (int q = 0; q < 4; q++) {
            int fi = tid + q * 128;
            int wk = fi >> 5, wn = (fi & 31) * 4;
            *(float4*)&Ws[wk][wn] = *(const float4*)(Wmat + (size_t)(k0 + wk) * FF + n0 + wn);
        }
        __syncthreads();
#pragma unroll
        for (int k = 0; k < 16; k++) {
            float a[8], w[8];
#pragma unroll
            for (int i = 0; i < 8; i++) a[i] = As[k][ty + i * 8];
#pragma unroll
            for (int jj = 0; jj < 8; jj++) w[jj] = Ws[k][tx + jj * 16];
#pragma unroll
            for (int i = 0; i < 8; i++)
#pragma unroll
                for (int jj = 0; jj < 8; jj++) acc[i][jj] = fmaf(a[i], w[jj], acc[i][jj]);
        }
        __syncthreads();
    }
#pragma unroll
    for (int i = 0; i < 8; i++) {
        int b = ty + i * 8;
        size_t base = ((size_t)b * 2 + j) * FF + n0;
#pragma unroll
        for (int jj = 0; jj < 8; jj++)
            g_part[c][base + tx + jj * 16] = acc[i][jj];
    }
}

// ===== scan pointwise + fused next-step gating =====
__global__ void k_point(int l, int t,
                        const float* __restrict__ bx, const float* __restrict__ bh,
                        const float* __restrict__ cb,
                        const float* __restrict__ aW, const float* __restrict__ ab) {
    const int b = blockIdx.x;
    const int u = threadIdx.x;      // 512
    const int wid = u >> 5, lane = u & 31;
    __shared__ float hsh[2][512];
    __shared__ float red[16][12];
    __shared__ float lg[12];
    const float* sharein = g_share[l];
    float* shareout = g_share[l + 1];
    float* hout = g_hid[l + 1];
    const size_t row = (size_t)b * TT + t;
    const float nxt = (t < TT - 1) ? 1.f : 0.f;
    const size_t rshift = (t < TT - 1) ? 1 : 0;

    float wv[2][KKC];
#pragma unroll
    for (int j = 0; j < 2; j++)
#pragma unroll
        for (int k = 0; k < KKC; k++) wv[j][k] = g_w[(b * 2 + j) * KKC + k];

    float sgsum = 0.f;
#pragma unroll
    for (int j = 0; j < 2; j++) {
        size_t p0 = ((size_t)j * ROWS + row) * FF;
        size_t p1 = ((size_t)j * ROWS + row + rshift) * FF;
        size_t qbase = ((size_t)b * 2 + j) * FF;
        float g[5];
#pragma unroll
        for (int gi = 0; gi < 5; gi++) {
            int f = gi * HH + u;
            float v = g_part[0][qbase + f] + g_part[1][qbase + f] + g_part[2][qbase + f];
            v += g_pre0[p0 + f];
            v += wv[j][1] * nxt * g_pre1[p1 + f] + wv[j][3] * g_pre2[p0 + f]
               + wv[j][4] * nxt * g_pre3[p1 + f] + wv[j][5] * g_pre4[p0 + f];
            size_t bidx = (size_t)(l * 2 + j) * FF + f;
            v += bx[bidx] + bh[bidx];
#pragma unroll
            for (int k = 0; k < KKC; k++)
                v += wv[j][k] * cb[((size_t)(l * 2 + j) * KKC + k) * FF + f];
            g[gi] = v;
        }
        size_t ci = (size_t)(b * 2 + j) * HH + u;
        float cell = g_cell[ci];
        float si = 1.f / (1.f + expf(-g[0]));
        float sf = 1.f / (1.f + expf(-g[1]));
        float so = 1.f / (1.f + expf(-g[2]));
        float cn = (1.f - sf) * cell + si * tanhf(g[4]);
        g_cell[ci] = cn;
        float h = so * tanhf(cn);
        hout[(row * 2 + j) * HH + u] = h;
        hsh[j][u] = h;
        sgsum += g[3];
    }
    float gate = 1.f / (1.f + expf(-sgsum));
    size_t su = (size_t)b * HH + u;
    float ss = g_sstate[su] + gate * sharein[row * HH + u];
    float cm = g_cum[su] + gate;
    g_sstate[su] = ss; g_cum[su] = cm;
    shareout[row * HH + u] = ss / cm;

    // ---- gating for step t+1 ----
    __syncthreads();
    float c01[12];
    {
        const float* ar = aW + ((size_t)l * HH + u) * KKC;
        float h0 = hsh[0][u], h1 = hsh[1][u];
#pragma unroll
        for (int k = 0; k < KKC; k++) { c01[k] = h0 * ar[k]; c01[6 + k] = h1 * ar[k]; }
    }
#pragma unroll
    for (int i = 0; i < 12; i++)
        for (int o = 16; o; o >>= 1) c01[i] += __shfl_down_sync(0xffffffffu, c01[i], o);
    if (lane == 0)
#pragma unroll
        for (int i = 0; i < 12; i++) red[wid][i] = c01[i];
    __syncthreads();
    if (u < 12) {
        float s = 0.f;
#pragma unroll
        for (int w = 0; w < 16; w++) s += red[w][u];
        lg[u] = s + ab[l * KKC + (u % KKC)];
    }
    __syncthreads();
    if (u < 2) {
        const float* L = &lg[u * 6];
        int i1 = 0;
        for (int k = 1; k < KKC; k++) if (L[k] > L[i1]) i1 = k;
        int i2 = (i1 == 0) ? 1 : 0;
        for (int k = 0; k < KKC; k++) if (k != i1 && L[k] > L[i2]) i2 = k;
#pragma unroll
        for (int k = 0; k < KKC; k++)
            g_w[(b * 2 + u) * KKC + k] = (k == i1 || k == i2) ? 0.5f : 0.f;
    }
}

// ===== final combine =====
__global__ void k_final(float* __restrict__ out) {
    size_t i = (size_t)blockIdx.x * blockDim.x + threadIdx.x;
    const size_t total = (size_t)BB * TT * 1536;
    if (i >= total) return;
    size_t bt = i / 1536;
    int f = (int)(i % 1536);
    float v;
    if (f < 1024)
        v = 0.5f * (g_hid[1][bt * 1024 + f] + g_hid[2][bt * 1024 + f]);
    else {
        int u = f - 1024;
        v = 0.5f * (g_share[1][bt * HH + u] + g_share[2][bt * HH + u]);
    }
    out[i] = v;
}

// ===== launch =====
extern "C" void kernel_launch(void* const* d_in, const int* in_sizes, int n_in,
                              void* d_out, int out_size) {
    (void)in_sizes; (void)n_in; (void)out_size;
    const float* feat = (const float*)d_in[0];
    const float* ctx  = (const float*)d_in[1];
    const float* l2sW = (const float*)d_in[2];
    const float* l2sb = (const float*)d_in[3];
    const float* sepW = (const float*)d_in[4];
    const float* sepb = (const float*)d_in[5];
    const float* aW   = (const float*)d_in[6];
    const float* ab   = (const float*)d_in[7];
    const float* Wx   = (const float*)d_in[8];
    const float* bx   = (const float*)d_in[9];
    const float* Wh   = (const float*)d_in[10];
    const float* bh   = (const float*)d_in[11];
    const float* Wc   = (const float*)d_in[12];
    const float* cb   = (const float*)d_in[13];
    float* out = (float*)d_out;

    k_share<<<dim3(4, 128), 128>>>(feat, l2sW, l2sb);
    k_groupsep<<<BB * TT, 128>>>(feat, sepW, sepb);
    k_ctxsplit<<<(ROWS * HH + 255) / 256, 256>>>(ctx);
    {
        size_t wtot = (size_t)20 * DDIM * FF;
        k_wsplit<<<(int)((wtot + 255) / 256), 256>>>(Wx, Wc);
    }
    for (int l = 0; l < LLAY; l++) {
        k_actsplit<<<(2 * ROWS * DDIM + 255) / 256, 256>>>(l);
        k_pre<<<dim3(20, 64, 10), 256>>>(l);
        k_layerinit<<<(BB * 2 * HH + 255) / 256, 256>>>(l, ab);
        for (int t = 0; t < TT; t++) {
            k_stepgemm<<<dim3(20, 2, 3), 128>>>(l, t, Wh, Wc);
            k_point<<<BB, 512>>>(l, t, bx, bh, cb, aW, ab);
        }
    }
    k_final<<<((BB * TT * 1536) + 255) / 256, 256>>>(out);
}